// round 16
// baseline (speedup 1.0000x reference)
#include <cuda_runtime.h>
#include <cuda_fp16.h>
#include <cstdint>

// ---------------------------------------------------------------------------
// Fixed problem dims
// ---------------------------------------------------------------------------
static constexpr int M = 8192;
static constexpr int K = 4096;
static constexpr int N = 11008;

// Scratch: xh = fp16(x); wh = fp16(W + 2*B@A)
__device__ __half g_Xh[(size_t)M * K];
__device__ __half g_Wh[(size_t)N * K];

// ---------------------------------------------------------------------------
// Interleaved prologue: groups of 4 blocks = 1 fold-W + 3 conv-X.
// Overlaps the FMA-heavy fold with the DRAM-bound conv inside every wave.
// ---------------------------------------------------------------------------
static constexpr int FO = 32;
static constexpr int FI = 512;
static constexpr int FOLD_BX = K / FI;             // 8
static constexpr int FOLD_BY = N / FO;             // 344
static constexpr int FOLD_BLOCKS = FOLD_BX * FOLD_BY;    // 2752
static constexpr int CONV_N4 = M * K / 4;                // 8388608 float4s
static constexpr int CONV_BLOCKS = CONV_N4 / 1024;       // 8192 (512thr x 2)
static constexpr int PRO_BLOCKS = FOLD_BLOCKS * 4;       // 11008 (3*2752=8256 conv slots)

__global__ __launch_bounds__(512)
void prologue_kernel(const float* __restrict__ X,
                     const float* __restrict__ W,
                     const float* __restrict__ Bm,
                     const float* __restrict__ Am) {
    const int tid = threadIdx.x;
    const int grp = blockIdx.x >> 2;
    const int sub = blockIdx.x & 3;

    if (sub != 0) {
        // ---- conv X block: index 3*grp + (sub-1), guard at 8192 ----
        int cb = 3 * grp + (sub - 1);
        if (cb >= CONV_BLOCKS) return;
        size_t base = (size_t)cb * 1024 + tid;
        const float4* X4 = reinterpret_cast<const float4*>(X);
        __half2* Xh2 = reinterpret_cast<__half2*>(g_Xh);
        float4 v0 = X4[base];
        float4 v1 = X4[base + 512];
        Xh2[2 * base]             = __floats2half2_rn(v0.x, v0.y);
        Xh2[2 * base + 1]         = __floats2half2_rn(v0.z, v0.w);
        Xh2[2 * (base + 512)]     = __floats2half2_rn(v1.x, v1.y);
        Xh2[2 * (base + 512) + 1] = __floats2half2_rn(v1.z, v1.w);
        return;
    }

    // ---- fold W block: Weff = W + 2*(B@A) -> fp16 ----
    __shared__ float sA[16][FI];
    __shared__ float sB[FO][16];
    const int bx = grp % FOLD_BX;
    const int by = grp / FOLD_BX;
    const int iBase = bx * FI;
    const int oBase = by * FO;

    for (int j = tid; j < 16 * FI; j += 512) {
        int r = j / FI, i = j % FI;
        sA[r][i] = Am[(size_t)r * K + iBase + i];
    }
    for (int j = tid; j < FO * 16; j += 512) {
        int o = j / 16, r = j % 16;
        sB[o][r] = Bm[(size_t)(oBase + o) * 16 + r];
    }
    __syncthreads();

    // FO*FI/4 = 4096 quads; 512 threads -> 8 quads each
    #pragma unroll
    for (int e = 0; e < (FO * FI) / (512 * 4); e++) {
        int q = tid + 512 * e;
        int oo = (q * 4) / FI, ii = (q * 4) % FI;
        size_t g = (size_t)(oBase + oo) * K + iBase + ii;
        float4 w4 = *reinterpret_cast<const float4*>(W + g);
        float a0 = w4.x, a1 = w4.y, a2 = w4.z, a3 = w4.w;
        #pragma unroll
        for (int r = 0; r < 16; r++) {
            float b2 = 2.0f * sB[oo][r];
            a0 += b2 * sA[r][ii];
            a1 += b2 * sA[r][ii + 1];
            a2 += b2 * sA[r][ii + 2];
            a3 += b2 * sA[r][ii + 3];
        }
        __half2* dst = reinterpret_cast<__half2*>(g_Wh + g);
        dst[0] = __floats2half2_rn(a0, a1);
        dst[1] = __floats2half2_rn(a2, a3);
    }
}

// ---------------------------------------------------------------------------
// Main GEMM (champion, byte-identical to R13/R15): C = Xh@Wh^T + bias
// CTA 128x256, 512 threads, 16 warps (4x4) of 32x64, BK=64, ldmatrix.x4,
// 3-stage cp.async, single barrier/stage, 1 CTA/SM, full 128-reg budget.
// SMEM rows: 144B stride; 144*i mod 128 covers all 8 phases -> conflict-free.
// ---------------------------------------------------------------------------
static constexpr int BM = 128, BN = 256, BK = 64;
static constexpr int TM_TILES = M / BM;   // 64
static constexpr int TN_TILES = N / BN;   // 43
static constexpr int NSTAGES_K = K / BK;  // 64

static constexpr int ROWB = 144;
static constexpr int TILE_X = BM * ROWB;              // 18432
static constexpr int TILE_W = BN * ROWB;              // 36864
static constexpr int OFF_X = 0;
static constexpr int OFF_W = TILE_X;
static constexpr int STAGE_BYTES = TILE_X + TILE_W;   // 55296
static constexpr int NSLOTS = 3;
static constexpr int SMEM_TOTAL = NSLOTS * STAGE_BYTES;  // 165888 (162KB)

#define MMA_FP16(d, a, b)                                                      \
    asm volatile(                                                              \
        "mma.sync.aligned.m16n8k16.row.col.f32.f16.f16.f32 "                   \
        "{%0,%1,%2,%3}, {%4,%5,%6,%7}, {%8,%9}, {%0,%1,%2,%3};"                \
        : "+f"((d)[0]), "+f"((d)[1]), "+f"((d)[2]), "+f"((d)[3])               \
        : "r"((a)[0]), "r"((a)[1]), "r"((a)[2]), "r"((a)[3]),                  \
          "r"((b)[0]), "r"((b)[1]))

#define LDSM_X4(r0, r1, r2, r3, addr)                                          \
    asm volatile("ldmatrix.sync.aligned.m8n8.x4.shared.b16 {%0,%1,%2,%3}, [%4];" \
                 : "=r"(r0), "=r"(r1), "=r"(r2), "=r"(r3) : "r"(addr))

__device__ __forceinline__ void cp16(uint32_t sdst, const void* g) {
    asm volatile("cp.async.cg.shared.global [%0], [%1], 16;" :: "r"(sdst), "l"(g));
}
#define CP_COMMIT() asm volatile("cp.async.commit_group;" ::: "memory")
#define CP_WAIT(n) asm volatile("cp.async.wait_group %0;" :: "n"(n) : "memory")

__device__ __forceinline__ void issue_stage(uint32_t tb, int k0,
                                            const __half* gX, const __half* gW,
                                            int tid) {
    // X: 128 rows x 8 chunks = 1024; W: 256 rows x 8 = 2048. 512 threads.
    #pragma unroll
    for (int j = 0; j < 2; j++) {
        int q = tid + 512 * j;
        int r = q >> 3, c = q & 7;
        cp16(tb + OFF_X + r * ROWB + c * 16, gX + (size_t)r * K + k0 + c * 8);
    }
    #pragma unroll
    for (int j = 0; j < 4; j++) {
        int q = tid + 512 * j;
        int r = q >> 3, c = q & 7;
        cp16(tb + OFF_W + r * ROWB + c * 16, gW + (size_t)r * K + k0 + c * 8);
    }
    CP_COMMIT();
}

__device__ __forceinline__ void compute_stage(uint32_t tb, int wm, int wn, int lane,
                                              float acc[2][8][4]) {
    const int lrow = lane & 15;
    const int lcol = lane >> 4;
    #pragma unroll
    for (int kk = 0; kk < 4; kk++) {
        const uint32_t kbyte = kk * 32 + lcol * 16;

        // B: warp covers 64 N-rows = 4 LDSM.x4 groups -> 8 n8 fragments
        uint32_t bh[8][2];
        #pragma unroll
        for (int np = 0; np < 4; np++) {
            uint32_t base = tb + OFF_W + (wn * 64 + np * 16 + lrow) * ROWB + kbyte;
            uint32_t t0, t1, t2, t3;
            LDSM_X4(t0, t1, t2, t3, base);
            bh[2 * np][0] = t0; bh[2 * np + 1][0] = t1;
            bh[2 * np][1] = t2; bh[2 * np + 1][1] = t3;
        }

        // A: 2 m16 tiles (warp covers 32 M-rows)
        #pragma unroll
        for (int mt = 0; mt < 2; mt++) {
            uint32_t base = tb + OFF_X + (wm * 32 + mt * 16 + lrow) * ROWB + kbyte;
            uint32_t ah[4];
            LDSM_X4(ah[0], ah[1], ah[2], ah[3], base);
            #pragma unroll
            for (int nt = 0; nt < 8; nt++) {
                MMA_FP16(acc[mt][nt], ah, bh[nt]);
            }
        }
    }
}

__global__ __launch_bounds__(512, 1)
void gemm_fp16_kernel(const float* __restrict__ bias, float* __restrict__ C) {
    extern __shared__ __align__(1024) char smem[];
    uint32_t sb;
    asm("{ .reg .u64 t; cvta.to.shared.u64 t, %1; cvt.u32.u64 %0, t; }"
        : "=r"(sb) : "l"(smem));

    const int tid = threadIdx.x;
    const int warp = tid >> 5;
    const int lane = tid & 31;
    const int wm = warp >> 2;  // 0..3 (32 rows each)
    const int wn = warp & 3;   // 0..3 (64 cols each)

    // Supertile raster: groups of 8 N-tiles, M-major within each group
    int lin = blockIdx.x;
    int gid = lin >> 9;             // / (8*64)
    int rem = lin & 511;
    int n0 = gid * 8;
    int width = min(8, TN_TILES - n0);
    int mT = rem / width;
    int nT = n0 + rem % width;
    const int mBase = mT * BM;
    const int nBase = nT * BN;

    const __half* gX = g_Xh + (size_t)mBase * K;
    const __half* gW = g_Wh + (size_t)nBase * K;

    float acc[2][8][4];
    #pragma unroll
    for (int a = 0; a < 2; a++)
        #pragma unroll
        for (int b = 0; b < 8; b++)
            #pragma unroll
            for (int c = 0; c < 4; c++) acc[a][b][c] = 0.0f;

    issue_stage(sb + 0 * STAGE_BYTES, 0 * BK, gX, gW, tid);
    issue_stage(sb + 1 * STAGE_BYTES, 1 * BK, gX, gW, tid);

    int slot = 0;
    for (int s = 0; s < NSTAGES_K; s++) {
        if (s + 1 < NSTAGES_K) { CP_WAIT(1); } else { CP_WAIT(0); }
        __syncthreads();   // single barrier: also guards reuse of slot
                           // (s+2)%3 == (s-1)%3, whose reads finished at s-1
        if (s + 2 < NSTAGES_K) {
            int wslot = slot + 2; if (wslot >= NSLOTS) wslot -= NSLOTS;
            issue_stage(sb + wslot * STAGE_BYTES, (s + 2) * BK, gX, gW, tid);
        }
        compute_stage(sb + slot * STAGE_BYTES, wm, wn, lane, acc);
        slot++;
        if (slot == NSLOTS) slot = 0;
    }

    // Epilogue: add bias, write fp32
    const int qrow = lane >> 2;
    const int qc = (lane & 3) * 2;
    #pragma unroll
    for (int nt = 0; nt < 8; nt++) {
        int col = nBase + wn * 64 + nt * 8 + qc;
        float2 bs = *(const float2*)(bias + col);
        #pragma unroll
        for (int mt = 0; mt < 2; mt++) {
            int row = mBase + wm * 32 + mt * 16 + qrow;
            float2 v0 = make_float2(acc[mt][nt][0] + bs.x, acc[mt][nt][1] + bs.y);
            float2 v1 = make_float2(acc[mt][nt][2] + bs.x, acc[mt][nt][3] + bs.y);
            *(float2*)(C + (size_t)row * N + col) = v0;
            *(float2*)(C + (size_t)(row + 8) * N + col) = v1;
        }
    }
}

// ---------------------------------------------------------------------------
// Launch
// ---------------------------------------------------------------------------
extern "C" void kernel_launch(void* const* d_in, const int* in_sizes, int n_in,
                              void* d_out, int out_size) {
    const float* x    = (const float*)d_in[0];
    const float* W    = (const float*)d_in[1];
    const float* bias = (const float*)d_in[2];
    const float* B    = (const float*)d_in[3];
    const float* A    = (const float*)d_in[4];
    float* out = (float*)d_out;

    prologue_kernel<<<PRO_BLOCKS, 512>>>(x, W, B, A);

    cudaFuncSetAttribute(gemm_fp16_kernel,
                         cudaFuncAttributeMaxDynamicSharedMemorySize, SMEM_TOTAL);
    gemm_fp16_kernel<<<TM_TILES * TN_TILES, 512, SMEM_TOTAL>>>(bias, out);
}

// round 17
// speedup vs baseline: 1.0046x; 1.0046x over previous
#include <cuda_runtime.h>
#include <cuda_fp16.h>
#include <cstdint>

// ---------------------------------------------------------------------------
// Fixed problem dims
// ---------------------------------------------------------------------------
static constexpr int M = 8192;
static constexpr int K = 4096;
static constexpr int N = 11008;

// Scratch: xh = fp16(x); wh = fp16(W + 2*B@A)
__device__ __half g_Xh[(size_t)M * K];
__device__ __half g_Wh[(size_t)N * K];

// ---------------------------------------------------------------------------
// Fused prologue (R15 layout): blocks [0, FOLD_BLOCKS) fold W; rest convert X.
// Fold inner loop now uses LDS.128 for sA (conflict-free) instead of 4x LDS.32
// with 4-way bank conflicts.
// ---------------------------------------------------------------------------
static constexpr int FO = 32;
static constexpr int FI = 512;
static constexpr int FOLD_BX = K / FI;            // 8
static constexpr int FOLD_BY = N / FO;            // 344
static constexpr int FOLD_BLOCKS = FOLD_BX * FOLD_BY;   // 2752
static constexpr int CONV_N4 = M * K / 4;               // 8388608 float4s
static constexpr int CONV_BLOCKS = CONV_N4 / 1024;      // 8192 (512 thr x 2)
static constexpr int PRO_BLOCKS = FOLD_BLOCKS + CONV_BLOCKS;

__global__ __launch_bounds__(512)
void prologue_kernel(const float* __restrict__ X,
                     const float* __restrict__ W,
                     const float* __restrict__ Bm,
                     const float* __restrict__ Am) {
    const int tid = threadIdx.x;
    if (blockIdx.x >= FOLD_BLOCKS) {
        // ---- convert X to fp16: 2 independent float4s per thread ----
        size_t base = (size_t)(blockIdx.x - FOLD_BLOCKS) * 1024 + tid;
        const float4* X4 = reinterpret_cast<const float4*>(X);
        __half2* Xh2 = reinterpret_cast<__half2*>(g_Xh);
        float4 v0 = X4[base];
        float4 v1 = X4[base + 512];
        Xh2[2 * base]             = __floats2half2_rn(v0.x, v0.y);
        Xh2[2 * base + 1]         = __floats2half2_rn(v0.z, v0.w);
        Xh2[2 * (base + 512)]     = __floats2half2_rn(v1.x, v1.y);
        Xh2[2 * (base + 512) + 1] = __floats2half2_rn(v1.z, v1.w);
        return;
    }

    // ---- fold W: Weff = W + 2*(B@A) -> fp16 ----
    __shared__ __align__(16) float sA[16][FI];
    __shared__ float sB[FO][16];
    const int bx = blockIdx.x % FOLD_BX;
    const int by = blockIdx.x / FOLD_BX;
    const int iBase = bx * FI;
    const int oBase = by * FO;

    for (int j = tid; j < 16 * FI; j += 512) {
        int r = j / FI, i = j % FI;
        sA[r][i] = Am[(size_t)r * K + iBase + i];
    }
    for (int j = tid; j < FO * 16; j += 512) {
        int o = j / 16, r = j % 16;
        sB[o][r] = Bm[(size_t)(oBase + o) * 16 + r];
    }
    __syncthreads();

    // FO*FI/4 = 4096 quads; 512 threads -> 8 quads each
    #pragma unroll
    for (int e = 0; e < (FO * FI) / (512 * 4); e++) {
        int q = tid + 512 * e;
        int oo = (q * 4) / FI, ii = (q * 4) % FI;
        size_t g = (size_t)(oBase + oo) * K + iBase + ii;
        float4 w4 = *reinterpret_cast<const float4*>(W + g);
        float a0 = w4.x, a1 = w4.y, a2 = w4.z, a3 = w4.w;
        #pragma unroll
        for (int r = 0; r < 16; r++) {
            float b2 = 2.0f * sB[oo][r];
            float4 a4 = *reinterpret_cast<const float4*>(&sA[r][ii]);  // LDS.128
            a0 += b2 * a4.x;
            a1 += b2 * a4.y;
            a2 += b2 * a4.z;
            a3 += b2 * a4.w;
        }
        __half2* dst = reinterpret_cast<__half2*>(g_Wh + g);
        dst[0] = __floats2half2_rn(a0, a1);
        dst[1] = __floats2half2_rn(a2, a3);
    }
}

// ---------------------------------------------------------------------------
// Main GEMM (champion, byte-identical to R13/R15): C = Xh@Wh^T + bias
// CTA 128x256, 512 threads, 16 warps (4x4) of 32x64, BK=64, ldmatrix.x4,
// 3-stage cp.async, single barrier/stage, 1 CTA/SM, full 128-reg budget.
// SMEM rows: 144B stride; 144*i mod 128 covers all 8 phases -> conflict-free.
// ---------------------------------------------------------------------------
static constexpr int BM = 128, BN = 256, BK = 64;
static constexpr int TM_TILES = M / BM;   // 64
static constexpr int TN_TILES = N / BN;   // 43
static constexpr int NSTAGES_K = K / BK;  // 64

static constexpr int ROWB = 144;
static constexpr int TILE_X = BM * ROWB;              // 18432
static constexpr int TILE_W = BN * ROWB;              // 36864
static constexpr int OFF_X = 0;
static constexpr int OFF_W = TILE_X;
static constexpr int STAGE_BYTES = TILE_X + TILE_W;   // 55296
static constexpr int NSLOTS = 3;
static constexpr int SMEM_TOTAL = NSLOTS * STAGE_BYTES;  // 165888 (162KB)

#define MMA_FP16(d, a, b)                                                      \
    asm volatile(                                                              \
        "mma.sync.aligned.m16n8k16.row.col.f32.f16.f16.f32 "                   \
        "{%0,%1,%2,%3}, {%4,%5,%6,%7}, {%8,%9}, {%0,%1,%2,%3};"                \
        : "+f"((d)[0]), "+f"((d)[1]), "+f"((d)[2]), "+f"((d)[3])               \
        : "r"((a)[0]), "r"((a)[1]), "r"((a)[2]), "r"((a)[3]),                  \
          "r"((b)[0]), "r"((b)[1]))

#define LDSM_X4(r0, r1, r2, r3, addr)                                          \
    asm volatile("ldmatrix.sync.aligned.m8n8.x4.shared.b16 {%0,%1,%2,%3}, [%4];" \
                 : "=r"(r0), "=r"(r1), "=r"(r2), "=r"(r3) : "r"(addr))

__device__ __forceinline__ void cp16(uint32_t sdst, const void* g) {
    asm volatile("cp.async.cg.shared.global [%0], [%1], 16;" :: "r"(sdst), "l"(g));
}
#define CP_COMMIT() asm volatile("cp.async.commit_group;" ::: "memory")
#define CP_WAIT(n) asm volatile("cp.async.wait_group %0;" :: "n"(n) : "memory")

__device__ __forceinline__ void issue_stage(uint32_t tb, int k0,
                                            const __half* gX, const __half* gW,
                                            int tid) {
    // X: 128 rows x 8 chunks = 1024; W: 256 rows x 8 = 2048. 512 threads.
    #pragma unroll
    for (int j = 0; j < 2; j++) {
        int q = tid + 512 * j;
        int r = q >> 3, c = q & 7;
        cp16(tb + OFF_X + r * ROWB + c * 16, gX + (size_t)r * K + k0 + c * 8);
    }
    #pragma unroll
    for (int j = 0; j < 4; j++) {
        int q = tid + 512 * j;
        int r = q >> 3, c = q & 7;
        cp16(tb + OFF_W + r * ROWB + c * 16, gW + (size_t)r * K + k0 + c * 8);
    }
    CP_COMMIT();
}

__device__ __forceinline__ void compute_stage(uint32_t tb, int wm, int wn, int lane,
                                              float acc[2][8][4]) {
    const int lrow = lane & 15;
    const int lcol = lane >> 4;
    #pragma unroll
    for (int kk = 0; kk < 4; kk++) {
        const uint32_t kbyte = kk * 32 + lcol * 16;

        // B: warp covers 64 N-rows = 4 LDSM.x4 groups -> 8 n8 fragments
        uint32_t bh[8][2];
        #pragma unroll
        for (int np = 0; np < 4; np++) {
            uint32_t base = tb + OFF_W + (wn * 64 + np * 16 + lrow) * ROWB + kbyte;
            uint32_t t0, t1, t2, t3;
            LDSM_X4(t0, t1, t2, t3, base);
            bh[2 * np][0] = t0; bh[2 * np + 1][0] = t1;
            bh[2 * np][1] = t2; bh[2 * np + 1][1] = t3;
        }

        // A: 2 m16 tiles (warp covers 32 M-rows)
        #pragma unroll
        for (int mt = 0; mt < 2; mt++) {
            uint32_t base = tb + OFF_X + (wm * 32 + mt * 16 + lrow) * ROWB + kbyte;
            uint32_t ah[4];
            LDSM_X4(ah[0], ah[1], ah[2], ah[3], base);
            #pragma unroll
            for (int nt = 0; nt < 8; nt++) {
                MMA_FP16(acc[mt][nt], ah, bh[nt]);
            }
        }
    }
}

__global__ __launch_bounds__(512, 1)
void gemm_fp16_kernel(const float* __restrict__ bias, float* __restrict__ C) {
    extern __shared__ __align__(1024) char smem[];
    uint32_t sb;
    asm("{ .reg .u64 t; cvta.to.shared.u64 t, %1; cvt.u32.u64 %0, t; }"
        : "=r"(sb) : "l"(smem));

    const int tid = threadIdx.x;
    const int warp = tid >> 5;
    const int lane = tid & 31;
    const int wm = warp >> 2;  // 0..3 (32 rows each)
    const int wn = warp & 3;   // 0..3 (64 cols each)

    // Supertile raster: groups of 8 N-tiles, M-major within each group
    int lin = blockIdx.x;
    int gid = lin >> 9;             // / (8*64)
    int rem = lin & 511;
    int n0 = gid * 8;
    int width = min(8, TN_TILES - n0);
    int mT = rem / width;
    int nT = n0 + rem % width;
    const int mBase = mT * BM;
    const int nBase = nT * BN;

    const __half* gX = g_Xh + (size_t)mBase * K;
    const __half* gW = g_Wh + (size_t)nBase * K;

    float acc[2][8][4];
    #pragma unroll
    for (int a = 0; a < 2; a++)
        #pragma unroll
        for (int b = 0; b < 8; b++)
            #pragma unroll
            for (int c = 0; c < 4; c++) acc[a][b][c] = 0.0f;

    issue_stage(sb + 0 * STAGE_BYTES, 0 * BK, gX, gW, tid);
    issue_stage(sb + 1 * STAGE_BYTES, 1 * BK, gX, gW, tid);

    int slot = 0;
    for (int s = 0; s < NSTAGES_K; s++) {
        if (s + 1 < NSTAGES_K) { CP_WAIT(1); } else { CP_WAIT(0); }
        __syncthreads();   // single barrier: also guards reuse of slot
                           // (s+2)%3 == (s-1)%3, whose reads finished at s-1
        if (s + 2 < NSTAGES_K) {
            int wslot = slot + 2; if (wslot >= NSLOTS) wslot -= NSLOTS;
            issue_stage(sb + wslot * STAGE_BYTES, (s + 2) * BK, gX, gW, tid);
        }
        compute_stage(sb + slot * STAGE_BYTES, wm, wn, lane, acc);
        slot++;
        if (slot == NSLOTS) slot = 0;
    }

    // Epilogue: add bias, write fp32
    const int qrow = lane >> 2;
    const int qc = (lane & 3) * 2;
    #pragma unroll
    for (int nt = 0; nt < 8; nt++) {
        int col = nBase + wn * 64 + nt * 8 + qc;
        float2 bs = *(const float2*)(bias + col);
        #pragma unroll
        for (int mt = 0; mt < 2; mt++) {
            int row = mBase + wm * 32 + mt * 16 + qrow;
            float2 v0 = make_float2(acc[mt][nt][0] + bs.x, acc[mt][nt][1] + bs.y);
            float2 v1 = make_float2(acc[mt][nt][2] + bs.x, acc[mt][nt][3] + bs.y);
            *(float2*)(C + (size_t)row * N + col) = v0;
            *(float2*)(C + (size_t)(row + 8) * N + col) = v1;
        }
    }
}

// ---------------------------------------------------------------------------
// Launch
// ---------------------------------------------------------------------------
extern "C" void kernel_launch(void* const* d_in, const int* in_sizes, int n_in,
                              void* d_out, int out_size) {
    const float* x    = (const float*)d_in[0];
    const float* W    = (const float*)d_in[1];
    const float* bias = (const float*)d_in[2];
    const float* B    = (const float*)d_in[3];
    const float* A    = (const float*)d_in[4];
    float* out = (float*)d_out;

    prologue_kernel<<<PRO_BLOCKS, 512>>>(x, W, B, A);

    cudaFuncSetAttribute(gemm_fp16_kernel,
                         cudaFuncAttributeMaxDynamicSharedMemorySize, SMEM_TOTAL);
    gemm_fp16_kernel<<<TM_TILES * TN_TILES, 512, SMEM_TOTAL>>>(bias, out);
}